// round 16
// baseline (speedup 1.0000x reference)
#include <cuda_runtime.h>
#include <cstdint>

#define NN     256
#define BB     8
#define SS     14
#define BS     (BB*SS)
#define NDAT   12      // S - len(PILOTS)
#define VMAX   4       // max members per work unit

// ---------------------------------------------------------------------------
// Single fused kernel with in-block dedup grouping.
// Grid = 448 blocks x 256 threads. Logical unit u = blockIdx>>2, part=blk&3.
// Units enumerate (unique cov index, chunk of <=4 member bs). Each block:
//   1. recomputes the bs->cov-index table + grouping (parallel scans, ~1K cyc)
//   2. streams 64 rows of cov[group] once via 2-deep LDG ring
//   3. computes V member DFTs in-block (overlaps ring fill)
//   4. dots each cov row with all V h vectors -> V outputs per row
// Worst case (all unique) NU=112 -> 448 blocks exactly; fewer => early exit.
// ---------------------------------------------------------------------------
__global__ void __launch_bounds__(256, 3)
fused_kernel(const float* __restrict__ xr,
             const float* __restrict__ xi,
             const float* __restrict__ cr,
             const float* __restrict__ ci,
             const float* __restrict__ zr,
             const float* __restrict__ zi,
             const int*   __restrict__ shift,
             const int*   __restrict__ gidx,
             float*       __restrict__ out)
{
    __shared__ int    s_idx[BS], s_rank[BS], s_cnt[BS], s_lead[BS];
    __shared__ int    s_map[2];          // leadbs (-1 if u>=NU), chunk
    __shared__ int    s_members[VMAX];
    __shared__ float2 xs[16 * 17];
    __shared__ float2 aa[17 * 16];
    __shared__ float2 w16[16];
    __shared__ float2 hT[VMAX * NN];     // hT[v][j*32+l] = h_v[8l+j]

    const int tid  = threadIdx.x;
    const int w    = tid >> 5;
    const int lane = tid & 31;
    const int u    = blockIdx.x >> 2;
    const int part = blockIdx.x & 3;

    if (tid < 16) {
        float sn, cs;
        sincospif(-(float)tid * 0.125f, &sn, &cs);   // e^{-2pi i t/16}
        w16[tid] = make_float2(cs, sn);
    }

    // ---- step 1: cov index for every bs ----
    if (tid < BS) {
        const int b = tid / SS, s = tid % SS;
        const int g = __ldg(&gidx[s]);
        s_idx[tid]  = (g == 0) ? 0 : __ldg(&shift[b * NDAT + g - 1]);
    }
    __syncthreads();

    // ---- step 2: parallel grouping scans ----
    if (tid < BS) {
        const int mine = s_idx[tid];
        int ld = tid, rk = 0, c = 0;
        for (int t2 = 0; t2 < BS; t2++) {
            if (s_idx[t2] == mine) {
                c++;
                if (t2 < tid) rk++;
                if (t2 < ld)  ld = t2;
            }
        }
        s_rank[tid] = rk;  s_cnt[tid] = c;  s_lead[tid] = ld;
    }
    __syncthreads();

    // ---- step 3: serial unit map (one thread, O(112)) ----
    if (tid == 0) {
        int acc = 0, lb = -1, ch = 0;
        for (int t2 = 0; t2 < BS; t2++) {
            if (s_lead[t2] == t2) {
                const int nc = (s_cnt[t2] + VMAX - 1) / VMAX;
                if (u >= acc && u < acc + nc) { lb = t2; ch = u - acc; }
                acc += nc;
            }
        }
        s_map[0] = lb;  s_map[1] = ch;
    }
    __syncthreads();

    const int leadbs = s_map[0];
    if (leadbs < 0) return;                       // u >= NU
    const int chunk  = s_map[1];
    const int covidx = s_idx[leadbs];
    const int V      = min(VMAX, s_cnt[leadbs] - chunk * VMAX);

    if (tid < BS && s_idx[tid] == covidx) {
        const int r = s_rank[tid] - chunk * VMAX;
        if (r >= 0 && r < VMAX) s_members[r] = tid;
    }
    __syncthreads();

    // ---- step 4: ring prologue (issue before DFT work) ----
    const size_t  base = (size_t)covidx * NN * NN;
    const float4* cr4  = (const float4*)(cr + base);
    const float4* ci4  = (const float4*)(ci + base);
    const int rowBase  = part * 64;

    float4 A[2][2], C[2][2];
#pragma unroll
    for (int p = 0; p < 2; p++) {
        const size_t ro = (size_t)(rowBase + p * 8 + w) * 64 + lane * 2;
        A[p][0] = cr4[ro];  A[p][1] = cr4[ro + 1];
        C[p][0] = ci4[ro];  C[p][1] = ci4[ro + 1];
    }

    // ---- step 5: V member DFTs (radix-16 x radix-16) -> hT ----
    for (int v = 0; v < V; v++) {
        const int bs = s_members[v];
        xs[(tid & 15) * 17 + (tid >> 4)] = make_float2(xr[bs * NN + tid],
                                                       xi[bs * NN + tid]);
        __syncthreads();

        {   // stage A
            const int k0 = tid >> 4, n0 = tid & 15;
            float ar = 0.0f, ai = 0.0f;
#pragma unroll
            for (int n1 = 0; n1 < 16; n1++) {
                const float2 vv = xs[n0 * 17 + n1];
                const float2 ww = w16[(k0 * n1) & 15];
                ar = fmaf(vv.x, ww.x, fmaf(-vv.y, ww.y, ar));
                ai = fmaf(vv.x, ww.y, fmaf( vv.y, ww.x, ai));
            }
            float sn, cs;
            sincospif(-(float)(k0 * n0) * (1.0f / 128.0f), &sn, &cs);
            aa[n0 * 17 + k0] = make_float2(ar * cs - ai * sn,
                                           ar * sn + ai * cs);
        }
        __syncthreads();

        {   // stage B + conj(zc); m == tid; transpose into hT
            const int k0 = tid & 15, k1 = tid >> 4;
            float Xr = 0.0f, Xi = 0.0f;
#pragma unroll
            for (int n0 = 0; n0 < 16; n0++) {
                const float2 vv = aa[n0 * 17 + k0];
                const float2 ww = w16[(k1 * n0) & 15];
                Xr = fmaf(vv.x, ww.x, fmaf(-vv.y, ww.y, Xr));
                Xi = fmaf(vv.x, ww.y, fmaf( vv.y, ww.x, Xi));
            }
            const float a  = zr[tid];
            const float bq = -zi[tid];
            hT[v * NN + (tid & 7) * 32 + (tid >> 3)] =
                make_float2(Xr * a - Xi * bq, Xr * bq + Xi * a);
        }
        __syncthreads();
    }

    // ---- step 6: stream 8 tiles; dot each row with V vectors ----
#pragma unroll
    for (int t = 0; t < 8; t++) {
        const int cur = t & 1;
        const float4 a0 = A[cur][0], a1 = A[cur][1];
        const float4 c0 = C[cur][0], c1 = C[cur][1];

        if (t < 6) {   // refill this stage with tile t+2
            const size_t ro = (size_t)(rowBase + (t + 2) * 8 + w) * 64 + lane * 2;
            A[cur][0] = cr4[ro];  A[cur][1] = cr4[ro + 1];
            C[cur][0] = ci4[ro];  C[cur][1] = ci4[ro + 1];
        }

        const int row = rowBase + t * 8 + w;

        for (int v = 0; v < V; v++) {
            const float2* hv = hT + v * NN;
            const float2 h0 = hv[0 * 32 + lane];
            const float2 h1 = hv[1 * 32 + lane];
            const float2 h2 = hv[2 * 32 + lane];
            const float2 h3 = hv[3 * 32 + lane];
            const float2 h4 = hv[4 * 32 + lane];
            const float2 h5 = hv[5 * 32 + lane];
            const float2 h6 = hv[6 * 32 + lane];
            const float2 h7 = hv[7 * 32 + lane];

            float re = 0.0f;
            re = fmaf(a0.x, h0.x, fmaf(-c0.x, h0.y, re));
            re = fmaf(a0.y, h1.x, fmaf(-c0.y, h1.y, re));
            re = fmaf(a0.z, h2.x, fmaf(-c0.z, h2.y, re));
            re = fmaf(a0.w, h3.x, fmaf(-c0.w, h3.y, re));
            re = fmaf(a1.x, h4.x, fmaf(-c1.x, h4.y, re));
            re = fmaf(a1.y, h5.x, fmaf(-c1.y, h5.y, re));
            re = fmaf(a1.z, h6.x, fmaf(-c1.z, h6.y, re));
            re = fmaf(a1.w, h7.x, fmaf(-c1.w, h7.y, re));

#pragma unroll
            for (int o = 16; o > 0; o >>= 1)
                re += __shfl_xor_sync(0xffffffffu, re, o);

            if (lane == 0) out[s_members[v] * NN + row] = re;
        }
    }
}

extern "C" void kernel_launch(void* const* d_in, const int* in_sizes, int n_in,
                              void* d_out, int out_size)
{
    const float* xr    = (const float*)d_in[0];
    const float* xi    = (const float*)d_in[1];
    const float* cr    = (const float*)d_in[2];
    const float* ci    = (const float*)d_in[3];
    const float* zr    = (const float*)d_in[4];
    const float* zi    = (const float*)d_in[5];
    const int*   shift = (const int*)d_in[6];
    const int*   gidx  = (const int*)d_in[7];

    fused_kernel<<<BS * 4, 256>>>(xr, xi, cr, ci, zr, zi, shift, gidx,
                                  (float*)d_out);
}